// round 1
// baseline (speedup 1.0000x reference)
#include <cuda_runtime.h>

// Problem constants (fixed by the reference)
#define BCONST 4
#define NTOK   16384
#define DIN    256
#define DOUT   512
#define HH     8
#define MMDIM  64
#define TTOT   (BCONST * NTOK)   // 65536 tokens

// ---------------- scratch (device globals; no runtime allocation) ----------
__device__ float g_q[(size_t)TTOT * DOUT];   // raw q projections
__device__ float g_k[(size_t)TTOT * DOUT];   // raw k projections
__device__ float g_v[(size_t)TTOT * DOUT];   // raw v projections
__device__ float g_KV[BCONST * HH * MMDIM * MMDIM];  // sum_n k_m v_d  per (b,h)
__device__ float g_kss[BCONST * HH * MMDIM];         // sum_n k
__device__ float g_vss[BCONST * HH * MMDIM];         // sum_n v
__device__ float g_sumsq[2];                         // [0]=||q||^2, [1]=||k||^2

// ---------------- helpers --------------------------------------------------
__device__ __forceinline__ unsigned long long fma2(unsigned long long a,
                                                   unsigned long long b,
                                                   unsigned long long c) {
    unsigned long long d;
    asm("fma.rn.f32x2 %0, %1, %2, %3;" : "=l"(d) : "l"(a), "l"(b), "l"(c));
    return d;
}
__device__ __forceinline__ float2 upk(unsigned long long v) {
    float2 r;
    asm("mov.b64 {%0, %1}, %2;" : "=f"(r.x), "=f"(r.y) : "l"(v));
    return r;
}

// ---------------- zero accumulators ----------------------------------------
__global__ void zero_acc_kernel() {
    int i = blockIdx.x * blockDim.x + threadIdx.x;
    const int KVSZ = BCONST * HH * MMDIM * MMDIM;   // 131072
    const int SSZ  = BCONST * HH * MMDIM;           // 2048
    if (i < KVSZ) g_KV[i] = 0.0f;
    if (i < SSZ) { g_kss[i] = 0.0f; g_vss[i] = 0.0f; }
    if (i < 2) g_sumsq[i] = 0.0f;
}

// ---------------- fused projection GEMM ------------------------------------
// Y[T, DOUT] = X[T, DIN] @ W[DOUT, DIN]^T + bias
// 128x128 tile, BK=8, 256 threads, 8x8 per thread via packed f32x2 FMA.
// Epilogue optionally accumulates sum(y^2) -> g_sumsq[sq_idx] and per-column
// sums -> sumptr (for ks_sum / vs_sum).
__global__ __launch_bounds__(256) void qkv_gemm_kernel(
    const float* __restrict__ X, const float* __restrict__ W,
    const float* __restrict__ bias, float* __restrict__ Y,
    int sq_idx, float* __restrict__ sumptr)
{
    __shared__ __align__(16) float Xs[8][256];  // duplicated: [k][2*m],[2*m+1]
    __shared__ __align__(16) float Ws[8][128];  // transposed: [k][o]
    __shared__ float csum[128];
    __shared__ float wred[8];

    const int tid = threadIdx.x;
    const int tx = tid & 15;          // output-col group
    const int ty = tid >> 4;          // output-row group
    const int rowbase = blockIdx.y * 128;
    const int colbase = blockIdx.x * 128;

    unsigned long long acc[8][4];
#pragma unroll
    for (int i = 0; i < 8; i++)
#pragma unroll
        for (int j = 0; j < 4; j++) acc[i][j] = 0ull;

    const int lm = tid >> 1;          // 0..127
    const int half = tid & 1;         // which 4-float chunk of the 8-wide k tile
    const float* xsrc = X + (size_t)(rowbase + lm) * DIN + half * 4;
    const float* wsrc = W + (size_t)(colbase + lm) * DIN + half * 4;

    for (int kb = 0; kb < DIN; kb += 8) {
        float4 xv = *(const float4*)(xsrc + kb);
        float4 wv = *(const float4*)(wsrc + kb);
        __syncthreads();
#pragma unroll
        for (int j = 0; j < 4; j++) {
            float v = (&xv.x)[j];
            Xs[half * 4 + j][2 * lm]     = v;   // duplicated A for pack-free
            Xs[half * 4 + j][2 * lm + 1] = v;   // f32x2 operands
            Ws[half * 4 + j][lm] = (&wv.x)[j];
        }
        __syncthreads();
#pragma unroll
        for (int k = 0; k < 8; k++) {
            const float* xk = &Xs[k][0];
            const float* wk = &Ws[k][0];
            ulonglong2 a01 = *(const ulonglong2*)(xk + 8 * ty);
            ulonglong2 a23 = *(const ulonglong2*)(xk + 8 * ty + 4);
            ulonglong2 a45 = *(const ulonglong2*)(xk + 8 * ty + 128);
            ulonglong2 a67 = *(const ulonglong2*)(xk + 8 * ty + 132);
            ulonglong2 b01 = *(const ulonglong2*)(wk + 4 * tx);
            ulonglong2 b23 = *(const ulonglong2*)(wk + 4 * tx + 64);
            unsigned long long ap[8] = {a01.x, a01.y, a23.x, a23.y,
                                        a45.x, a45.y, a67.x, a67.y};
            unsigned long long bp[4] = {b01.x, b01.y, b23.x, b23.y};
#pragma unroll
            for (int i = 0; i < 8; i++)
#pragma unroll
                for (int j = 0; j < 4; j++)
                    acc[i][j] = fma2(ap[i], bp[j], acc[i][j]);
        }
    }

    // ---- epilogue: bias, store, fused reductions ----
    float bj[8];
#pragma unroll
    for (int j = 0; j < 4; j++) {
        bj[j]     = bias[colbase + tx * 4 + j];
        bj[4 + j] = bias[colbase + 64 + tx * 4 + j];
    }

    float ss = 0.0f;
    float cs[8];
#pragma unroll
    for (int j = 0; j < 8; j++) cs[j] = 0.0f;

#pragma unroll
    for (int i = 0; i < 8; i++) {
        int r = rowbase + ((i < 4) ? (ty * 4 + i) : (64 + ty * 4 + (i - 4)));
        float y[8];
        float2 p0 = upk(acc[i][0]); y[0] = p0.x; y[1] = p0.y;
        float2 p1 = upk(acc[i][1]); y[2] = p1.x; y[3] = p1.y;
        float2 p2 = upk(acc[i][2]); y[4] = p2.x; y[5] = p2.y;
        float2 p3 = upk(acc[i][3]); y[6] = p3.x; y[7] = p3.y;
#pragma unroll
        for (int j = 0; j < 8; j++) {
            y[j] += bj[j];
            ss += y[j] * y[j];
            cs[j] += y[j];
        }
        float4 o0 = make_float4(y[0], y[1], y[2], y[3]);
        float4 o1 = make_float4(y[4], y[5], y[6], y[7]);
        *(float4*)&Y[(size_t)r * DOUT + colbase + tx * 4]      = o0;
        *(float4*)&Y[(size_t)r * DOUT + colbase + 64 + tx * 4] = o1;
    }

    if (sq_idx >= 0) {
#pragma unroll
        for (int o = 16; o > 0; o >>= 1) ss += __shfl_xor_sync(0xffffffffu, ss, o);
        if ((tid & 31) == 0) wred[tid >> 5] = ss;
    }
    __syncthreads();
    if (sq_idx >= 0 && tid == 0) {
        float t = 0.0f;
#pragma unroll
        for (int w = 0; w < 8; w++) t += wred[w];
        atomicAdd(&g_sumsq[sq_idx], t);
    }

    if (sumptr) {   // uniform branch across the block
        if (tid < 128) csum[tid] = 0.0f;
        __syncthreads();
#pragma unroll
        for (int j = 0; j < 4; j++) {
            atomicAdd(&csum[tx * 4 + j],      cs[j]);
            atomicAdd(&csum[64 + tx * 4 + j], cs[4 + j]);
        }
        __syncthreads();
        if (tid < 128) {
            int cg = colbase + tid;
            int b  = rowbase / NTOK;
            int h  = cg / MMDIM, m = cg % MMDIM;
            atomicAdd(&sumptr[(b * HH + h) * MMDIM + m], csum[tid]);
        }
    }
}

// ---------------- KV accumulation: KV[b,h] = K_bh^T @ V_bh ------------------
// grid (B*H, 8 chunks), 256 threads, 4x4 per thread over (m,d).
__global__ __launch_bounds__(256) void kv_kernel() {
    __shared__ __align__(16) float Ks[16][64];
    __shared__ __align__(16) float Vs[16][64];
    const int tid = threadIdx.x;
    const int tx = tid & 15, ty = tid >> 4;
    const int bh = blockIdx.x;
    const int b = bh >> 3, h = bh & 7;
    const int n0 = blockIdx.y * (NTOK / 8);   // 2048 tokens per CTA

    float acc[4][4] = {};
    const int tt = tid >> 4;             // staging token within 16-tile
    const int c4 = (tid & 15) * 4;       // staging column
    const size_t base = ((size_t)(b * NTOK + n0)) * DOUT + h * 64;

    for (int t0 = 0; t0 < NTOK / 8; t0 += 16) {
        float4 kv4 = *(const float4*)&g_k[base + (size_t)(t0 + tt) * DOUT + c4];
        float4 vv4 = *(const float4*)&g_v[base + (size_t)(t0 + tt) * DOUT + c4];
        __syncthreads();
        *(float4*)&Ks[tt][c4] = kv4;
        *(float4*)&Vs[tt][c4] = vv4;
        __syncthreads();
#pragma unroll
        for (int t = 0; t < 16; t++) {
            float4 a4 = *(const float4*)&Ks[t][ty * 4];
            float4 b4 = *(const float4*)&Vs[t][tx * 4];
#pragma unroll
            for (int i = 0; i < 4; i++)
#pragma unroll
                for (int j = 0; j < 4; j++)
                    acc[i][j] += (&a4.x)[i] * (&b4.x)[j];
        }
    }
    float* dst = &g_KV[((size_t)bh * MMDIM + ty * 4) * MMDIM + tx * 4];
#pragma unroll
    for (int i = 0; i < 4; i++)
#pragma unroll
        for (int j = 0; j < 4; j++)
            atomicAdd(&dst[i * MMDIM + j], acc[i][j]);
}

// ---------------- output kernel --------------------------------------------
// out[b,n,d] = (1/H) sum_h (q·KV[b,h][:,d]·c + vs_sum) / (q·ks_sum·c + N)
// One CTA = 128 tokens of one batch b; KV[b] (all 8 heads) cached in smem.
// Each warp processes 16 tokens in groups of 4 (shares KV smem loads 4-ways).
__global__ __launch_bounds__(256) void out_kernel(float* __restrict__ out) {
    extern __shared__ __align__(16) float sm[];
    float* KVs  = sm;            // 32768 floats
    float* kss  = sm + 32768;    // 512
    float* vss  = sm + 33280;    // 512
    float* qbuf = sm + 33792;    // 8 warps * 4 tokens * 512 = 16384

    const int tid = threadIdx.x, lane = tid & 31, warp = tid >> 5;
    const int tok0 = blockIdx.x * 128;
    const int b = tok0 / NTOK;

    const float* KVsrc = g_KV + (size_t)b * HH * MMDIM * MMDIM;
    for (int i = tid * 4; i < HH * MMDIM * MMDIM; i += 256 * 4)
        *(float4*)&KVs[i] = *(const float4*)&KVsrc[i];
    for (int i = tid; i < HH * MMDIM; i += 256) {
        kss[i] = g_kss[b * HH * MMDIM + i];
        vss[i] = g_vss[b * HH * MMDIM + i];
    }
    __syncthreads();

    const float cscale = rsqrtf(g_sumsq[0] * g_sumsq[1]);  // 1/(||q|| ||k||)
    float* qw = qbuf + warp * 2048;
    const int wt0 = tok0 + warp * 16;

    for (int g = 0; g < 4; g++) {
        const int t0 = wt0 + g * 4;
        __syncwarp();
        // stage 4 q rows (4*512 floats) -> 16 float4 per lane, coalesced
#pragma unroll
        for (int r = 0; r < 16; r++) {
            int fi = r * 32 + lane;            // float4 index 0..511
            int tk = fi >> 7;                  // token within group
            int off = (fi & 127) * 4;
            *(float4*)&qw[tk * 512 + off] =
                *(const float4*)&g_q[(size_t)(t0 + tk) * DOUT + off];
        }
        __syncwarp();

        float a0[4] = {0, 0, 0, 0}, a1[4] = {0, 0, 0, 0};
#pragma unroll
        for (int h = 0; h < HH; h++) {
            const float* kvh = &KVs[h * 4096];
            const float* qh0 = qw + h * 64;
            float kl  = kss[h * 64 + lane];
            float kh2 = kss[h * 64 + lane + 32];

            float nd[4];
#pragma unroll
            for (int t = 0; t < 4; t++) {
                float qa  = qh0[t * 512 + lane];
                float qb2 = qh0[t * 512 + lane + 32];
                nd[t] = qa * kl + qb2 * kh2;
            }
#pragma unroll
            for (int o = 16; o > 0; o >>= 1)
#pragma unroll
                for (int t = 0; t < 4; t++)
                    nd[t] += __shfl_xor_sync(0xffffffffu, nd[t], o);

            float n0[4] = {0, 0, 0, 0}, n1[4] = {0, 0, 0, 0};
#pragma unroll
            for (int m4 = 0; m4 < 16; m4++) {
                float4 q4[4];
#pragma unroll
                for (int t = 0; t < 4; t++)
                    q4[t] = *(const float4*)&qh0[t * 512 + m4 * 4];
#pragma unroll
                for (int j = 0; j < 4; j++) {
                    float kv0 = kvh[(m4 * 4 + j) * 64 + lane];
                    float kv1 = kvh[(m4 * 4 + j) * 64 + lane + 32];
#pragma unroll
                    for (int t = 0; t < 4; t++) {
                        float qm = (&q4[t].x)[j];
                        n0[t] += qm * kv0;
                        n1[t] += qm * kv1;
                    }
                }
            }
            float v0 = vss[h * 64 + lane], v1 = vss[h * 64 + lane + 32];
#pragma unroll
            for (int t = 0; t < 4; t++) {
                float den = nd[t] * cscale + (float)NTOK;
                float rden = 1.0f / den;
                a0[t] += (n0[t] * cscale + v0) * rden;
                a1[t] += (n1[t] * cscale + v1) * rden;
            }
        }
#pragma unroll
        for (int t = 0; t < 4; t++) {
            out[(size_t)(t0 + t) * MMDIM + lane]      = a0[t] * 0.125f;
            out[(size_t)(t0 + t) * MMDIM + lane + 32] = a1[t] * 0.125f;
        }
    }
}

// ---------------- launch ----------------------------------------------------
extern "C" void kernel_launch(void* const* d_in, const int* in_sizes, int n_in,
                              void* d_out, int out_size) {
    (void)in_sizes; (void)n_in; (void)out_size;
    const float* qin  = (const float*)d_in[0];
    const float* sin_ = (const float*)d_in[1];
    const float* Wq   = (const float*)d_in[2];
    const float* bq   = (const float*)d_in[3];
    const float* Wk   = (const float*)d_in[4];
    const float* bk   = (const float*)d_in[5];
    const float* Wv   = (const float*)d_in[6];
    const float* bv   = (const float*)d_in[7];
    float* out = (float*)d_out;

    float *pq, *pk, *pv, *pkss, *pvss;
    cudaGetSymbolAddress((void**)&pq,   g_q);
    cudaGetSymbolAddress((void**)&pk,   g_k);
    cudaGetSymbolAddress((void**)&pv,   g_v);
    cudaGetSymbolAddress((void**)&pkss, g_kss);
    cudaGetSymbolAddress((void**)&pvss, g_vss);

    zero_acc_kernel<<<512, 256>>>();

    dim3 gg(DOUT / 128, TTOT / 128);   // (4, 512)
    qkv_gemm_kernel<<<gg, 256>>>(qin,  Wq, bq, pq,  0, nullptr);
    qkv_gemm_kernel<<<gg, 256>>>(sin_, Wk, bk, pk,  1, pkss);
    qkv_gemm_kernel<<<gg, 256>>>(sin_, Wv, bv, pv, -1, pvss);

    kv_kernel<<<dim3(BCONST * HH, 8), 256>>>();

    const int SMEM_OUT = 50176 * 4;    // 200704 bytes
    cudaFuncSetAttribute(out_kernel,
                         cudaFuncAttributeMaxDynamicSharedMemorySize, SMEM_OUT);
    out_kernel<<<TTOT / 128, 256, SMEM_OUT>>>(out);
}

// round 4
// speedup vs baseline: 1.3233x; 1.3233x over previous
#include <cuda_runtime.h>

// Problem constants (fixed by the reference)
#define BCONST 4
#define NTOK   16384
#define DIN    256
#define DOUT   512
#define HH     8
#define MMDIM  64
#define TTOT   (BCONST * NTOK)   // 65536 tokens

// ---------------- scratch (device globals; no runtime allocation) ----------
__device__ float g_q[(size_t)TTOT * DOUT];   // raw q projections
__device__ float g_k[(size_t)TTOT * DOUT];   // raw k projections
__device__ float g_v[(size_t)TTOT * DOUT];   // raw v projections
__device__ float g_KV[BCONST * HH * MMDIM * MMDIM];  // sum_n k_m v_d  per (b,h)
__device__ float g_kss[BCONST * HH * MMDIM];         // sum_n k
__device__ float g_vss[BCONST * HH * MMDIM];         // sum_n v
__device__ float g_sumsq[2];                         // [0]=||q||^2, [1]=||k||^2

// ---------------- helpers --------------------------------------------------
__device__ __forceinline__ unsigned long long fma2(unsigned long long a,
                                                   unsigned long long b,
                                                   unsigned long long c) {
    unsigned long long d;
    asm("fma.rn.f32x2 %0, %1, %2, %3;" : "=l"(d) : "l"(a), "l"(b), "l"(c));
    return d;
}
__device__ __forceinline__ float2 upk(unsigned long long v) {
    float2 r;
    asm("mov.b64 {%0, %1}, %2;" : "=f"(r.x), "=f"(r.y) : "l"(v));
    return r;
}
__device__ __forceinline__ unsigned long long dup2(float a) {
    unsigned long long r;
    asm("mov.b64 %0, {%1, %1};" : "=l"(r) : "f"(a));
    return r;
}

// ---------------- zero accumulators ----------------------------------------
__global__ void zero_acc_kernel() {
    int i = blockIdx.x * blockDim.x + threadIdx.x;
    const int KVSZ = BCONST * HH * MMDIM * MMDIM;   // 131072
    const int SSZ  = BCONST * HH * MMDIM;           // 2048
    if (i < KVSZ) g_KV[i] = 0.0f;
    if (i < SSZ) { g_kss[i] = 0.0f; g_vss[i] = 0.0f; }
    if (i < 2) g_sumsq[i] = 0.0f;
}

// ---------------- fused projection GEMM ------------------------------------
// Y[T, DOUT] = X[T, DIN] @ W[DOUT, DIN]^T + bias
// 128x128 tile, BK=8, 256 threads, 8x8 per thread via packed f32x2 FMA.
// A stored ONCE in smem (no duplication); f32x2 dup pairs built with mov.b64.
// Epilogue optionally accumulates sum(y^2) -> g_sumsq[sq_idx] and per-column
// sums -> sumptr (for ks_sum / vs_sum).
__global__ __launch_bounds__(256) void qkv_gemm_kernel(
    const float* __restrict__ X, const float* __restrict__ W,
    const float* __restrict__ bias, float* __restrict__ Y,
    int sq_idx, float* __restrict__ sumptr)
{
    __shared__ __align__(16) float Xs[8][128];
    __shared__ __align__(16) float Ws[8][128];
    __shared__ float csum[128];
    __shared__ float wred[8];

    const int tid = threadIdx.x;
    const int tx = tid & 15;          // output-col group
    const int ty = tid >> 4;          // output-row group
    const int rowbase = blockIdx.y * 128;
    const int colbase = blockIdx.x * 128;

    unsigned long long acc[8][4];
#pragma unroll
    for (int i = 0; i < 8; i++)
#pragma unroll
        for (int j = 0; j < 4; j++) acc[i][j] = 0ull;

    const int lm = tid >> 1;          // 0..127
    const int half = tid & 1;         // which 4-float chunk of the 8-wide k tile
    const float* xsrc = X + (size_t)(rowbase + lm) * DIN + half * 4;
    const float* wsrc = W + (size_t)(colbase + lm) * DIN + half * 4;

    float4 xv = *(const float4*)(xsrc);
    float4 wv = *(const float4*)(wsrc);

    for (int kb = 0; kb < DIN; kb += 8) {
        __syncthreads();
#pragma unroll
        for (int j = 0; j < 4; j++) {
            Xs[half * 4 + j][lm] = (&xv.x)[j];
            Ws[half * 4 + j][lm] = (&wv.x)[j];
        }
        __syncthreads();
        if (kb + 8 < DIN) {            // prefetch next k-block
            xv = *(const float4*)(xsrc + kb + 8);
            wv = *(const float4*)(wsrc + kb + 8);
        }
#pragma unroll
        for (int k = 0; k < 8; k++) {
            const float* xk = &Xs[k][0];
            const float* wk = &Ws[k][0];
            float4 al = *(const float4*)(xk + 4 * ty);
            float4 ah = *(const float4*)(xk + 64 + 4 * ty);
            ulonglong2 b01 = *(const ulonglong2*)(wk + 4 * tx);
            ulonglong2 b23 = *(const ulonglong2*)(wk + 64 + 4 * tx);
            unsigned long long ap[8] = {dup2(al.x), dup2(al.y), dup2(al.z), dup2(al.w),
                                        dup2(ah.x), dup2(ah.y), dup2(ah.z), dup2(ah.w)};
            unsigned long long bp[4] = {b01.x, b01.y, b23.x, b23.y};
#pragma unroll
            for (int i = 0; i < 8; i++)
#pragma unroll
                for (int j = 0; j < 4; j++)
                    acc[i][j] = fma2(ap[i], bp[j], acc[i][j]);
        }
    }

    // ---- epilogue: bias, store, fused reductions ----
    float bj[8];
#pragma unroll
    for (int j = 0; j < 4; j++) {
        bj[j]     = bias[colbase + tx * 4 + j];
        bj[4 + j] = bias[colbase + 64 + tx * 4 + j];
    }

    float ss = 0.0f;
    float cs[8];
#pragma unroll
    for (int j = 0; j < 8; j++) cs[j] = 0.0f;

#pragma unroll
    for (int i = 0; i < 8; i++) {
        int r = rowbase + ((i < 4) ? (ty * 4 + i) : (64 + ty * 4 + (i - 4)));
        float y[8];
        float2 p0 = upk(acc[i][0]); y[0] = p0.x; y[1] = p0.y;
        float2 p1 = upk(acc[i][1]); y[2] = p1.x; y[3] = p1.y;
        float2 p2 = upk(acc[i][2]); y[4] = p2.x; y[5] = p2.y;
        float2 p3 = upk(acc[i][3]); y[6] = p3.x; y[7] = p3.y;
#pragma unroll
        for (int j = 0; j < 8; j++) {
            y[j] += bj[j];
            ss += y[j] * y[j];
            cs[j] += y[j];
        }
        float4 o0 = make_float4(y[0], y[1], y[2], y[3]);
        float4 o1 = make_float4(y[4], y[5], y[6], y[7]);
        *(float4*)&Y[(size_t)r * DOUT + colbase + tx * 4]      = o0;
        *(float4*)&Y[(size_t)r * DOUT + colbase + 64 + tx * 4] = o1;
    }

    if (sq_idx >= 0) {
#pragma unroll
        for (int o = 16; o > 0; o >>= 1) ss += __shfl_xor_sync(0xffffffffu, ss, o);
        if ((tid & 31) == 0) wred[tid >> 5] = ss;
    }
    __syncthreads();
    if (sq_idx >= 0 && tid == 0) {
        float t = 0.0f;
#pragma unroll
        for (int w = 0; w < 8; w++) t += wred[w];
        atomicAdd(&g_sumsq[sq_idx], t);
    }

    if (sumptr) {   // uniform branch across the block
        if (tid < 128) csum[tid] = 0.0f;
        __syncthreads();
#pragma unroll
        for (int j = 0; j < 4; j++) {
            atomicAdd(&csum[tx * 4 + j],      cs[j]);
            atomicAdd(&csum[64 + tx * 4 + j], cs[4 + j]);
        }
        __syncthreads();
        if (tid < 128) {
            int cg = colbase + tid;
            int b  = rowbase / NTOK;
            int h  = cg / MMDIM, m = cg % MMDIM;
            atomicAdd(&sumptr[(b * HH + h) * MMDIM + m], csum[tid]);
        }
    }
}

// ---------------- KV accumulation: KV[b,h] = K_bh^T @ V_bh ------------------
// grid (B*H, 8 chunks), 256 threads, 4x4 per thread over (m,d).
__global__ __launch_bounds__(256) void kv_kernel() {
    __shared__ __align__(16) float Ks[16][64];
    __shared__ __align__(16) float Vs[16][64];
    const int tid = threadIdx.x;
    const int tx = tid & 15, ty = tid >> 4;
    const int bh = blockIdx.x;
    const int b = bh >> 3, h = bh & 7;
    const int n0 = blockIdx.y * (NTOK / 8);   // 2048 tokens per CTA

    float acc[4][4] = {};
    const int tt = tid >> 4;             // staging token within 16-tile
    const int c4 = (tid & 15) * 4;       // staging column
    const size_t base = ((size_t)(b * NTOK + n0)) * DOUT + h * 64;

    for (int t0 = 0; t0 < NTOK / 8; t0 += 16) {
        float4 kv4 = *(const float4*)&g_k[base + (size_t)(t0 + tt) * DOUT + c4];
        float4 vv4 = *(const float4*)&g_v[base + (size_t)(t0 + tt) * DOUT + c4];
        __syncthreads();
        *(float4*)&Ks[tt][c4] = kv4;
        *(float4*)&Vs[tt][c4] = vv4;
        __syncthreads();
#pragma unroll
        for (int t = 0; t < 16; t++) {
            float4 a4 = *(const float4*)&Ks[t][ty * 4];
            float4 b4 = *(const float4*)&Vs[t][tx * 4];
#pragma unroll
            for (int i = 0; i < 4; i++)
#pragma unroll
                for (int j = 0; j < 4; j++)
                    acc[i][j] += (&a4.x)[i] * (&b4.x)[j];
        }
    }
    float* dst = &g_KV[((size_t)bh * MMDIM + ty * 4) * MMDIM + tx * 4];
#pragma unroll
    for (int i = 0; i < 4; i++)
#pragma unroll
        for (int j = 0; j < 4; j++)
            atomicAdd(&dst[i * MMDIM + j], acc[i][j]);
}

// ---------------- output kernel (microtiled batched GEMM) -------------------
// out[b,n,d] = (1/H) sum_h (q·KV[b,h][:,d]·c + vs_sum) / (q·ks_sum·c + N)
// CTA = 128 tokens of one batch. All-head KV + sums staged once; per head we
// stage the 128x64 Q slice (row-major, padded), precompute reciprocal
// denominators, then run a 128x64x64 microtiled GEMM (8 tok x 4 d per thread,
// all smem traffic LDS.128, packed f32x2 accumulation across heads).
#define QPAD 68
__global__ __launch_bounds__(256) void out_kernel(float* __restrict__ out) {
    extern __shared__ __align__(16) float sm[];
    float* KVs = sm;                   // 32768
    float* kss = sm + 32768;           // 512
    float* vss = sm + 33280;           // 512
    float* Qs  = sm + 33792;           // 128*68 = 8704
    float* den = sm + 33792 + 128 * QPAD;  // 128  (stores 1/denominator)

    const int tid = threadIdx.x;
    const int tx = tid & 15;           // d group (4 cols)
    const int ty = tid >> 4;           // token group (8 rows)
    const int tok0 = blockIdx.x * 128;
    const int b = tok0 / NTOK;

    const float* KVsrc = g_KV + (size_t)b * HH * MMDIM * MMDIM;
    for (int i = tid * 4; i < HH * MMDIM * MMDIM; i += 256 * 4)
        *(float4*)&KVs[i] = *(const float4*)&KVsrc[i];
    for (int i = tid; i < HH * MMDIM; i += 256) {
        kss[i] = g_kss[b * HH * MMDIM + i];
        vss[i] = g_vss[b * HH * MMDIM + i];
    }
    const float cscale = rsqrtf(g_sumsq[0] * g_sumsq[1]);  // 1/(||q|| ||k||)
    const unsigned long long cdup = dup2(cscale);

    unsigned long long oacc[8][2];
#pragma unroll
    for (int i = 0; i < 8; i++) { oacc[i][0] = 0ull; oacc[i][1] = 0ull; }

    for (int h = 0; h < HH; h++) {
        __syncthreads();   // previous head's reads done (also covers initial stage)
        // stage Q slice [128 tokens x 64 m], row-major padded to QPAD
#pragma unroll
        for (int i = 0; i < 8; i++) {
            int f = tid + i * 256;         // float4 index 0..2047
            int r = f >> 4;
            int c4 = (f & 15) * 4;
            float4 qv = *(const float4*)&g_q[(size_t)(tok0 + r) * DOUT + h * 64 + c4];
            *(float4*)&Qs[r * QPAD + c4] = qv;
        }
        __syncthreads();
        // reciprocal denominators per token
        if (tid < 128) {
            float d = 0.0f;
#pragma unroll
            for (int m4 = 0; m4 < 16; m4++) {
                float4 q4 = *(const float4*)&Qs[tid * QPAD + m4 * 4];
                d += q4.x * kss[h * 64 + m4 * 4 + 0];
                d += q4.y * kss[h * 64 + m4 * 4 + 1];
                d += q4.z * kss[h * 64 + m4 * 4 + 2];
                d += q4.w * kss[h * 64 + m4 * 4 + 3];
            }
            den[tid] = 1.0f / (d * cscale + (float)NTOK);
        }
        __syncthreads();

        // GEMM: N[128x64] = Qh[128x64] @ KVh[64x64]
        unsigned long long acc[8][2];
#pragma unroll
        for (int i = 0; i < 8; i++) { acc[i][0] = 0ull; acc[i][1] = 0ull; }
        const float* kvh = &KVs[h * 4096];

#pragma unroll 4
        for (int m0 = 0; m0 < 64; m0 += 4) {
            float4 a4[8];
#pragma unroll
            for (int i = 0; i < 4; i++) {
                a4[i]     = *(const float4*)&Qs[(4 * ty + i) * QPAD + m0];
                a4[4 + i] = *(const float4*)&Qs[(64 + 4 * ty + i) * QPAD + m0];
            }
#pragma unroll
            for (int mm = 0; mm < 4; mm++) {
                ulonglong2 bb = *(const ulonglong2*)&kvh[(m0 + mm) * 64 + 4 * tx];
#pragma unroll
                for (int i = 0; i < 8; i++) {
                    unsigned long long ad = dup2((&a4[i].x)[mm]);
                    acc[i][0] = fma2(ad, bb.x, acc[i][0]);
                    acc[i][1] = fma2(ad, bb.y, acc[i][1]);
                }
            }
        }

        // epilogue: oacc += (acc*c + vs_sum) * rden
        ulonglong2 vvp = *(const ulonglong2*)&vss[h * 64 + 4 * tx];
        unsigned long long vp[2] = {vvp.x, vvp.y};
#pragma unroll
        for (int i = 0; i < 8; i++) {
            int row = (i < 4) ? (4 * ty + i) : (64 + 4 * ty + (i - 4));
            unsigned long long rdup = dup2(den[row]);
#pragma unroll
            for (int j = 0; j < 2; j++) {
                unsigned long long t = fma2(acc[i][j], cdup, vp[j]);
                oacc[i][j] = fma2(t, rdup, oacc[i][j]);
            }
        }
    }

    // final store: mean over heads
#pragma unroll
    for (int i = 0; i < 8; i++) {
        int row = (i < 4) ? (4 * ty + i) : (64 + 4 * ty + (i - 4));
        float2 p0 = upk(oacc[i][0]);
        float2 p1 = upk(oacc[i][1]);
        float4 o = make_float4(p0.x * 0.125f, p0.y * 0.125f,
                               p1.x * 0.125f, p1.y * 0.125f);
        *(float4*)&out[(size_t)(tok0 + row) * MMDIM + 4 * tx] = o;
    }
}

// ---------------- launch ----------------------------------------------------
extern "C" void kernel_launch(void* const* d_in, const int* in_sizes, int n_in,
                              void* d_out, int out_size) {
    (void)in_sizes; (void)n_in; (void)out_size;
    const float* qin  = (const float*)d_in[0];
    const float* sin_ = (const float*)d_in[1];
    const float* Wq   = (const float*)d_in[2];
    const float* bq   = (const float*)d_in[3];
    const float* Wk   = (const float*)d_in[4];
    const float* bk   = (const float*)d_in[5];
    const float* Wv   = (const float*)d_in[6];
    const float* bv   = (const float*)d_in[7];
    float* out = (float*)d_out;

    float *pq, *pk, *pv, *pkss, *pvss;
    cudaGetSymbolAddress((void**)&pq,   g_q);
    cudaGetSymbolAddress((void**)&pk,   g_k);
    cudaGetSymbolAddress((void**)&pv,   g_v);
    cudaGetSymbolAddress((void**)&pkss, g_kss);
    cudaGetSymbolAddress((void**)&pvss, g_vss);

    zero_acc_kernel<<<512, 256>>>();

    dim3 gg(DOUT / 128, TTOT / 128);   // (4, 512)
    qkv_gemm_kernel<<<gg, 256>>>(qin,  Wq, bq, pq,  0, nullptr);
    qkv_gemm_kernel<<<gg, 256>>>(sin_, Wk, bk, pk,  1, pkss);
    qkv_gemm_kernel<<<gg, 256>>>(sin_, Wv, bv, pv, -1, pvss);

    kv_kernel<<<dim3(BCONST * HH, 8), 256>>>();

    const int SMEM_OUT = (33792 + 128 * QPAD + 128) * 4;   // 170,496 bytes
    cudaFuncSetAttribute(out_kernel,
                         cudaFuncAttributeMaxDynamicSharedMemorySize, SMEM_OUT);
    out_kernel<<<TTOT / 128, 256, SMEM_OUT>>>(out);
}